// round 2
// baseline (speedup 1.0000x reference)
#include <cuda_runtime.h>
#include <cuda_bf16.h>
#include <cstdint>

#define DEV_INLINE __device__ __forceinline__

constexpr int Bb = 8;
constexpr int Nn = 4096;
constexpr int Jj = 64;     // P*W
constexpr int Kf = 128;    // M*A

// ---------------- static device scratch (no allocation) ----------------
__device__ float    g_h32[Bb * Nn * Jj];          // h fp32 (8 MB)
__device__ unsigned g_hpk_hi[Bb * (Nn/2) * Jj];   // h hi bf16, node-pair packed (4 MB)
__device__ unsigned g_hpk_lo[Bb * (Nn/2) * Jj];   // h lo residual bf16 (4 MB)

DEV_INLINE unsigned pack2(float f0, float f1) {   // f0 -> low 16 bits
    __nv_bfloat162 t = __floats2bfloat162_rn(f0, f1);
    return *reinterpret_cast<unsigned*>(&t);
}

// ============================================================================
// Kernel 1: h[b,n,j] = sum_{m,a} x[b,n,m,a]*W[m,p(j),a,w(j)]; emit fp32 h and
// bf16 hi/lo packed over node pairs (GEMM-B fragment-ready layout).
// ============================================================================
__global__ void __launch_bounds__(128)
spconv_h_kernel(const float* __restrict__ x, const float* __restrict__ wgt)
{
    __shared__ float ws[Kf * Jj];   // ws[(m*32+a)*64 + j]
    const int b = blockIdx.y;
    const int n = blockIdx.x * 128 + threadIdx.x;

    for (int idx = threadIdx.x; idx < Kf * Jj; idx += 128) {
        int ka = idx >> 6, j = idx & 63;
        int m = ka >> 5, a = ka & 31, p = j >> 4, w = j & 15;
        ws[idx] = wgt[(((m * 4 + p) * 32 + a) << 4) + w];
    }
    __syncthreads();

    float acc[64];
#pragma unroll
    for (int j = 0; j < 64; j++) acc[j] = 0.f;

    const float* xrow = x + (size_t)(b * Nn + n) * Kf;
#pragma unroll 1
    for (int m = 0; m < 4; m++) {
        float xr[32];
#pragma unroll
        for (int i = 0; i < 8; i++) {
            float4 v = *(const float4*)(xrow + m * 32 + i * 4);
            xr[i*4+0]=v.x; xr[i*4+1]=v.y; xr[i*4+2]=v.z; xr[i*4+3]=v.w;
        }
#pragma unroll 4
        for (int a = 0; a < 32; a++) {
            const float xa = xr[a];
            const float4* wrow = (const float4*)&ws[(m * 32 + a) * 64];
#pragma unroll
            for (int j4 = 0; j4 < 16; j4++) {
                float4 wv = wrow[j4];
                acc[j4*4+0] = fmaf(xa, wv.x, acc[j4*4+0]);
                acc[j4*4+1] = fmaf(xa, wv.y, acc[j4*4+1]);
                acc[j4*4+2] = fmaf(xa, wv.z, acc[j4*4+2]);
                acc[j4*4+3] = fmaf(xa, wv.w, acc[j4*4+3]);
            }
        }
    }

    float* hp = g_h32 + (size_t)(b * Nn + n) * Jj;
#pragma unroll
    for (int j4 = 0; j4 < 16; j4++)
        *(float4*)(hp + j4*4) = make_float4(acc[j4*4+0], acc[j4*4+1],
                                            acc[j4*4+2], acc[j4*4+3]);

    const size_t pbase = ((size_t)(b * (Nn/2) + (n >> 1))) * Jj;
#pragma unroll 4
    for (int j = 0; j < 64; j++) {
        float v1 = __shfl_xor_sync(0xffffffffu, acc[j], 1);
        if ((threadIdx.x & 1) == 0) {
            float v0 = acc[j];
            __nv_bfloat16 h0 = __float2bfloat16_rn(v0);
            __nv_bfloat16 h1 = __float2bfloat16_rn(v1);
            g_hpk_hi[pbase + j] = (unsigned)__bfloat16_as_ushort(h0)
                                | ((unsigned)__bfloat16_as_ushort(h1) << 16);
            g_hpk_lo[pbase + j] = pack2(v0 - __bfloat162float(h0),
                                        v1 - __bfloat162float(h1));
        }
    }
}

// ============================================================================
// Kernel 2: per-batch C = adj @ h with fused rowsum / normalize / self-loop /
// relu / bias. 3-pass bf16 split mma. BM=128 BN=64 BK=32, 256 threads.
// ============================================================================
constexpr int A_STR = 20;                 // u32 stride per A row (16 kpairs + 4 pad)
constexpr int B_STR = 72;                 // u32 stride per B kpair row (64 + 8 pad)
constexpr int A_STAGE = 128 * A_STR;      // 2560 u32
constexpr int B_STAGE = 16 * B_STR;       // 1152 u32
constexpr int OFF_AH = 0;
constexpr int OFF_AL = 2 * A_STAGE;       // 5120
constexpr int OFF_BH = 4 * A_STAGE;       // 10240
constexpr int OFF_BL = OFF_BH + 2 * B_STAGE; // 12544
constexpr int SMEM_U32 = OFF_BL + 2 * B_STAGE; // 14848
constexpr int SMEM_BYTES = SMEM_U32 * 4;  // 59392

DEV_INLINE void mma_bf16(float* c, const unsigned* a, const unsigned* b) {
    asm volatile(
        "mma.sync.aligned.m16n8k16.row.col.f32.bf16.bf16.f32 "
        "{%0,%1,%2,%3}, {%4,%5,%6,%7}, {%8,%9}, {%0,%1,%2,%3};\n"
        : "+f"(c[0]), "+f"(c[1]), "+f"(c[2]), "+f"(c[3])
        : "r"(a[0]), "r"(a[1]), "r"(a[2]), "r"(a[3]), "r"(b[0]), "r"(b[1]));
}

DEV_INLINE void ldsm4(unsigned* r, uint32_t addr) {
    asm volatile(
        "ldmatrix.sync.aligned.m8n8.x4.shared.b16 {%0,%1,%2,%3}, [%4];\n"
        : "=r"(r[0]), "=r"(r[1]), "=r"(r[2]), "=r"(r[3]) : "r"(addr));
}

__global__ void __launch_bounds__(256, 2)
spconv_gemm_kernel(const float* __restrict__ adj, const float* __restrict__ bias,
                   float* __restrict__ out)
{
    extern __shared__ unsigned sm[];
    const uint32_t smb = (uint32_t)__cvta_generic_to_shared(sm);

    const int t    = threadIdx.x;
    const int lane = t & 31, warp = t >> 5;
    const int g = lane >> 2, tg = lane & 3;
    const int wrow = warp >> 1, wcol = warp & 1;
    const int bx = blockIdx.x, b = blockIdx.y;

    // ldmatrix lane address components
    const int lm_row = (lane & 7) + ((lane >> 3) & 1) * 8;
    const int lm_kp  = ((lane >> 4) & 1) * 4;

    // A staging: thread loads rows (t>>3)+32p, cols (t&7)*4..+3
    const int ar = t >> 3, ac4 = (t & 7) * 4, akp = (t & 7) * 2;
    const float* adj_base = adj + ((size_t)b * Nn + (size_t)bx * 128 + ar) * Nn + ac4;
    // B staging: thread copies u32 [t*4 .. t*4+3]: kpair=t>>4, n=(t&15)*4
    const int bkp = t >> 4, bn4 = (t & 15) * 4;
    const unsigned* hpH = g_hpk_hi + ((size_t)b * 2048) * 64 + bkp * 64 + bn4;
    const unsigned* hpL = g_hpk_lo + ((size_t)b * 2048) * 64 + bkp * 64 + bn4;

    float acc[2][4][4];
#pragma unroll
    for (int mf = 0; mf < 2; mf++)
#pragma unroll
        for (int nf = 0; nf < 4; nf++)
#pragma unroll
            for (int i = 0; i < 4; i++) acc[mf][nf][i] = 0.f;

    float rsum[4] = {0.f, 0.f, 0.f, 0.f};
    float4 va[4];
    uint4 vbh, vbl;

    auto ldgA = [&](int kt) {
#pragma unroll
        for (int p = 0; p < 4; p++)
            va[p] = *(const float4*)(adj_base + (size_t)(p * 32) * Nn + kt * 32);
    };
    auto ldgB = [&](int kt) {
        vbh = *(const uint4*)(hpH + (size_t)kt * 16 * 64);
        vbl = *(const uint4*)(hpL + (size_t)kt * 16 * 64);
    };
    auto stsAll = [&](int s) {
        unsigned* Ah = sm + OFF_AH + s * A_STAGE;
        unsigned* Al = sm + OFF_AL + s * A_STAGE;
#pragma unroll
        for (int p = 0; p < 4; p++) {
            float4 v = va[p];
            rsum[p] += (v.x + v.y) + (v.z + v.w);
            __nv_bfloat16 bx0 = __float2bfloat16_rn(v.x);
            __nv_bfloat16 bx1 = __float2bfloat16_rn(v.y);
            __nv_bfloat16 bx2 = __float2bfloat16_rn(v.z);
            __nv_bfloat16 bx3 = __float2bfloat16_rn(v.w);
            unsigned h0 = (unsigned)__bfloat16_as_ushort(bx0)
                        | ((unsigned)__bfloat16_as_ushort(bx1) << 16);
            unsigned h1 = (unsigned)__bfloat16_as_ushort(bx2)
                        | ((unsigned)__bfloat16_as_ushort(bx3) << 16);
            unsigned l0 = pack2(v.x - __bfloat162float(bx0), v.y - __bfloat162float(bx1));
            unsigned l1 = pack2(v.z - __bfloat162float(bx2), v.w - __bfloat162float(bx3));
            int idx = (ar + 32 * p) * A_STR + akp;
            *(uint2*)(Ah + idx) = make_uint2(h0, h1);
            *(uint2*)(Al + idx) = make_uint2(l0, l1);
        }
        unsigned* Bh = sm + OFF_BH + s * B_STAGE;
        unsigned* Bl = sm + OFF_BL + s * B_STAGE;
        *(uint4*)(Bh + bkp * B_STR + bn4) = vbh;
        *(uint4*)(Bl + bkp * B_STR + bn4) = vbl;
    };
    auto compute = [&](int s) {
        const unsigned* Bh = sm + OFF_BH + s * B_STAGE;
        const unsigned* Bl = sm + OFF_BL + s * B_STAGE;
        const uint32_t ahb = smb + (OFF_AH + s * A_STAGE) * 4;
        const uint32_t alb = smb + (OFF_AL + s * A_STAGE) * 4;
#pragma unroll
        for (int ks = 0; ks < 2; ks++) {
            unsigned bh[4][2], bl[4][2];
#pragma unroll
            for (int nf = 0; nf < 4; nf++) {
                int n = wcol * 32 + nf * 8 + g;
                int k0 = (ks * 8 + tg) * B_STR + n;
                bh[nf][0] = Bh[k0];            bh[nf][1] = Bh[k0 + 4 * B_STR];
                bl[nf][0] = Bl[k0];            bl[nf][1] = Bl[k0 + 4 * B_STR];
            }
#pragma unroll
            for (int mf = 0; mf < 2; mf++) {
                int aoff = ((wrow * 32 + mf * 16 + lm_row) * A_STR + ks * 8 + lm_kp) * 4;
                unsigned ah[4], al[4];
                ldsm4(ah, ahb + aoff);
                ldsm4(al, alb + aoff);
#pragma unroll
                for (int nf = 0; nf < 4; nf++) {
                    mma_bf16(acc[mf][nf], ah, bh[nf]);
                    mma_bf16(acc[mf][nf], al, bh[nf]);
                    mma_bf16(acc[mf][nf], ah, bl[nf]);
                }
            }
        }
    };

    // ---- pipeline ----
    ldgA(0); ldgB(0);
    stsAll(0);
    __syncthreads();
#pragma unroll 1
    for (int kt = 0; kt < 128; kt++) {
        const int cur = kt & 1;
        if (kt < 127) { ldgA(kt + 1); ldgB(kt + 1); }
        compute(cur);
        if (kt < 127) {
            __syncthreads();
            stsAll(1 - cur);
            __syncthreads();
        }
    }
    __syncthreads();

    // ---- rowsum reduce (alias A smem region) ----
    float* rs   = (float*)sm;            // [128][9]
    float* rinv = (float*)(sm + 1200);   // [128]
#pragma unroll
    for (int p = 0; p < 4; p++) rs[(ar + 32 * p) * 9 + (t & 7)] = rsum[p];
    __syncthreads();
    if (t < 128) {
        float s = 1.0f;  // self loop
#pragma unroll
        for (int i = 0; i < 8; i++) s += rs[t * 9 + i];
        rinv[t] = 1.0f / s;
    }
    __syncthreads();

    // ---- epilogue: out = relu((S + h)*rinv) + bias ----
#pragma unroll
    for (int mf = 0; mf < 2; mf++) {
#pragma unroll
        for (int nf = 0; nf < 4; nf++) {
            int r0 = wrow * 32 + mf * 16 + g;
            int c  = wcol * 32 + nf * 8 + 2 * tg;
            float ri0 = rinv[r0], ri1 = rinv[r0 + 8];
            int gr0 = bx * 128 + r0;
            size_t o0 = ((size_t)b * Nn + gr0) * 64 + c;
            size_t o1 = o0 + (size_t)8 * 64;
            float2 h0 = *(const float2*)(g_h32 + o0);
            float2 h1 = *(const float2*)(g_h32 + o1);
            float bz0 = __ldg(bias + c), bz1 = __ldg(bias + c + 1);
            float2 w0, w1;
            w0.x = fmaxf((acc[mf][nf][0] + h0.x) * ri0, 0.f) + bz0;
            w0.y = fmaxf((acc[mf][nf][1] + h0.y) * ri0, 0.f) + bz1;
            w1.x = fmaxf((acc[mf][nf][2] + h1.x) * ri1, 0.f) + bz0;
            w1.y = fmaxf((acc[mf][nf][3] + h1.y) * ri1, 0.f) + bz1;
            *(float2*)(out + o0) = w0;
            *(float2*)(out + o1) = w1;
        }
    }
}

// ============================================================================
extern "C" void kernel_launch(void* const* d_in, const int* in_sizes, int n_in,
                              void* d_out, int out_size)
{
    const float* x    = (const float*)d_in[0];
    const float* adj  = (const float*)d_in[1];
    const float* wgt  = (const float*)d_in[2];
    const float* bias = (const float*)d_in[3];
    float* out = (float*)d_out;

    cudaFuncSetAttribute(spconv_gemm_kernel,
                         cudaFuncAttributeMaxDynamicSharedMemorySize, SMEM_BYTES);

    spconv_h_kernel<<<dim3(32, 8), 128>>>(x, wgt);
    spconv_gemm_kernel<<<dim3(32, 8), 256, SMEM_BYTES>>>(adj, bias, out);
}